// round 16
// baseline (speedup 1.0000x reference)
#include <cuda_runtime.h>
#include <cuda_fp16.h>
#include <cstdint>

// Shapes fixed by the problem.
#define BB 16
#define CC 64
#define HH 64
#define WW 64
#define CO 64
#define KT 9    // 3x3 taps

// Scratch (__device__ globals: allocation-free rule).
__device__ __half g_nhwc_h[BB * HH * WW * CC];   // [b][y][x][c], fp16
// B fragments (fp16) pre-packed in mma register order:
// idx4 = ((k*4+ks)*4+j)*32 + lane ; uint4 = {nt=2j:(b0,b1), nt=2j+1:(b0,b1)}
__device__ uint4 g_bf[KT * 4 * 4 * 32];          // 4608 uint4 = 72KB

// ---------------------------------------------------------------------------
// helpers
// ---------------------------------------------------------------------------
__device__ __forceinline__ uint32_t smem_u32(const void* p) {
    uint32_t a;
    asm("{ .reg .u64 t; cvta.to.shared.u64 t, %1; cvt.u32.u64 %0, t; }" : "=r"(a) : "l"(p));
    return a;
}
__device__ __forceinline__ void ldsm4(uint32_t* r, uint32_t addr) {
    asm volatile("ldmatrix.sync.aligned.m8n8.x4.shared.b16 {%0,%1,%2,%3}, [%4];"
                 : "=r"(r[0]), "=r"(r[1]), "=r"(r[2]), "=r"(r[3]) : "r"(addr));
}
__device__ __forceinline__ void mma16816h(float* c, const uint32_t* a, uint32_t b0, uint32_t b1) {
    asm volatile("mma.sync.aligned.m16n8k16.row.col.f32.f16.f16.f32 "
                 "{%0,%1,%2,%3}, {%4,%5,%6,%7}, {%8,%9}, {%0,%1,%2,%3};"
                 : "+f"(c[0]), "+f"(c[1]), "+f"(c[2]), "+f"(c[3])
                 : "r"(a[0]), "r"(a[1]), "r"(a[2]), "r"(a[3]), "r"(b0), "r"(b1));
}
__device__ __forceinline__ uint32_t pack_half(float x, float y) {
    __half2 p = __floats2half2_rn(x, y);   // x -> low half
    return *reinterpret_cast<uint32_t*>(&p);
}
__device__ __forceinline__ __half2 u2h2(uint32_t u) {
    return *reinterpret_cast<__half2*>(&u);
}
__device__ __forceinline__ void pf_l1(const void* p) {
    asm volatile("prefetch.global.L1 [%0];" :: "l"(p));
}

// ---------------------------------------------------------------------------
// Kernel 1 (merged): blocks [0,1024): NCHW f32 -> NHWC fp16 transpose
//                    blocks [1024,1042): weight -> fp16 B fragments (reg order)
// ---------------------------------------------------------------------------
__global__ void prep_kernel(const float* __restrict__ in, const float* __restrict__ w) {
    if (blockIdx.x < 1024) {
        __shared__ float tile[64][65];
        int by = blockIdx.x;
        int b = by >> 6, y = by & 63;
        #pragma unroll
        for (int i = threadIdx.x; i < 64 * 16; i += 256) {     // float4 loads
            int c = i >> 4, x4 = (i & 15) * 4;
            float4 v = *(const float4*)(in + (((b * 64 + c) * 64 + y) * 64) + x4);
            tile[c][x4 + 0] = v.x; tile[c][x4 + 1] = v.y;
            tile[c][x4 + 2] = v.z; tile[c][x4 + 3] = v.w;
        }
        __syncthreads();
        #pragma unroll
        for (int i = threadIdx.x; i < 64 * 16; i += 256) {     // uint2 stores
            int x = i >> 4, cq = i & 15;
            int c0 = cq * 4;
            uint2 o;
            o.x = pack_half(tile[c0][x],     tile[c0 + 1][x]);
            o.y = pack_half(tile[c0 + 2][x], tile[c0 + 3][x]);
            *reinterpret_cast<uint2*>(g_nhwc_h + (((b * 64 + y) * 64 + x) * 64) + c0) = o;
        }
    } else {
        int idx = (blockIdx.x - 1024) * 256 + threadIdx.x;     // 18 blocks: 4608
        if (idx >= KT * 4 * 4 * 32) return;
        int lane = idx & 31;
        int t = idx >> 5;
        int j  = t & 3;
        int ks = (t >> 2) & 3;
        int k  = t >> 4;
        uint32_t r32[4];
        #pragma unroll
        for (int cmp = 0; cmp < 4; cmp++) {
            int nt = j * 2 + (cmp >> 1);
            int r  = cmp & 1;
            int n  = nt * 8 + (lane >> 2);
            int kk = ks * 16 + r * 8 + (lane & 3) * 2;
            float v0 = w[(n * 64 + kk    ) * 9 + k];
            float v1 = w[(n * 64 + kk + 1) * 9 + k];
            r32[cmp] = pack_half(v0, v1);
        }
        g_bf[idx] = make_uint4(r32[0], r32[1], r32[2], r32[3]);
    }
}

// ---------------------------------------------------------------------------
// Kernel 2: fused deformable sampling (HFMA2) + fp16 HMMA.
// CTA = 64 threads = 2 fully independent warps; tile = 64 px (ONE image row).
// uint4 gather (8 ch/lane, 8 lanes/px), 1-stage data pipeline PLUS an L1
// prefetch stream 2 iterations ahead (zero register cost) to convert
// L2-hit gather stalls (~234cyc) into L1 hits.
// ---------------------------------------------------------------------------
#define A_STRIDE 144   // bytes per A row (72 fp16: pad 64->72, conflict-free ldmatrix)
#define A_REGION 9216  // 64 rows x 144B
#define META_OFF A_REGION

__global__ __launch_bounds__(64, 8)
void dcn_main_kernel(const float* __restrict__ offset,  // (B,18,H,W)
                     const float* __restrict__ mask,    // (B,9,H,W)
                     const float* __restrict__ bias,    // (Cout,)
                     float* __restrict__ out)           // (B,Cout,H,W)
{
    extern __shared__ __align__(16) char smem[];
    char* A_t   = smem;                        // 64 x 144B = 9216
    uint4* Meta = (uint4*)(smem + META_OFF);   // [px] {wAB, wCD, pk01, pk23}

    const int tid  = threadIdx.x;
    const int wid  = tid >> 5;     // 0,1
    const int lane = tid & 31;
    const int tx8  = lane & 7;     // c-chunk (c = tx8*8)
    const int q    = lane >> 3;    // quarter-warp (0..3)

    const int b = blockIdx.x >> 6;
    const int p = blockIdx.x & 63;             // image row

    const uint32_t a_u = smem_u32(A_t);
    const __half* in_b = g_nhwc_h + (size_t)b * 262144;

    // Per-lane pixel and strided offset/mask pointers (k-stride constant).
    const int px_own = wid * 32 + lane;        // 0..63 (column within row p)
    const float* offp = offset + (size_t)b * 18 * 4096 + p * 64 + px_own;
    const float* mskp = mask   + (size_t)b * 9 * 4096  + p * 64 + px_own;

    float acc[2][8][4];
    #pragma unroll
    for (int mi = 0; mi < 2; mi++)
        #pragma unroll
        for (int nt = 0; nt < 8; nt++)
            #pragma unroll
            for (int r = 0; r < 4; r++) acc[mi][nt][r] = 0.f;

    // Pipeline stage: tap-0 offset/mask.
    float nx_oy = offp[0];
    float nx_ox = offp[4096];
    float nx_m  = mskp[0];

    for (int k = 0; k < 9; k++) {
        // ---- consume preloaded offsets; issue tap k+1's loads ----
        float oy = nx_oy, ox = nx_ox, m = nx_m;
        if (k < 8) {
            nx_oy = offp[(k + 1) * 8192];
            nx_ox = offp[(k + 1) * 8192 + 4096];
            nx_m  = mskp[(k + 1) * 4096];
        }

        // ---- per-pixel tap precompute -> meta smem (STS.128, one px per lane) ----
        {
            float py  = oy + (float)(p - 1 + (k / 3));
            float pxx = ox + (float)(px_own - 1 + (k % 3));
            float y0f = floorf(py), x0f = floorf(pxx);
            float wy = py - y0f, wx = pxx - x0f;
            int y0 = (int)y0f, x0 = (int)x0f;
            int y1 = y0 + 1,   x1 = x0 + 1;
            float vy0 = (y0 >= 0 && y0 < 64) ? 1.f : 0.f;
            float vy1 = (y1 >= 0 && y1 < 64) ? 1.f : 0.f;
            float vx0 = (x0 >= 0 && x0 < 64) ? 1.f : 0.f;
            float vx1 = (x1 >= 0 && x1 < 64) ? 1.f : 0.f;
            int y0c = min(max(y0, 0), 63), y1c = min(max(y1, 0), 63);
            int x0c = min(max(x0, 0), 63), x1c = min(max(x1, 0), 63);
            float w0 = m * (1.f - wy) * (1.f - wx) * vy0 * vx0;
            float w1 = m * (1.f - wy) * wx         * vy0 * vx1;
            float w2 = m * wy         * (1.f - wx) * vy1 * vx0;
            float w3 = m * wy         * wx         * vy1 * vx1;
            uint4 mv;
            mv.x = pack_half(w0, w1);
            mv.y = pack_half(w2, w3);
            mv.z = (uint32_t)(y0c * 64 + x0c) | ((uint32_t)(y0c * 64 + x1c) << 16);
            mv.w = (uint32_t)(y1c * 64 + x0c) | ((uint32_t)(y1c * 64 + x1c) << 16);
            Meta[px_own] = mv;
        }
        __syncwarp();   // meta visible to whole warp

        // ---- sampling: 1-stage data pipeline + 2-ahead L1 prefetch stream ----
        {
            const __half* in_c = in_b + tx8 * 8;
            const uint4* mwarp = Meta + wid * 32 + q * 8;    // this quarter's px stream

            uint4 mt = mwarp[0];
            uint4 u0 = *(const uint4*)(in_c + ((int)(mt.z & 0xFFFFu) << 6));
            uint4 u1 = *(const uint4*)(in_c + ((int)(mt.z >> 16) << 6));
            uint4 u2 = *(const uint4*)(in_c + ((int)(mt.w & 0xFFFFu) << 6));
            uint4 u3 = *(const uint4*)(in_c + ((int)(mt.w >> 16) << 6));

            #pragma unroll
            for (int i = 0; i < 8; i++) {
                uint4 mt_n;
                uint4 v0, v1, v2, v3;
                if (i < 7) {   // 1-stage data prefetch (meta + 4 gathers)
                    mt_n = mwarp[i + 1];
                    v0 = *(const uint4*)(in_c + ((int)(mt_n.z & 0xFFFFu) << 6));
                    v1 = *(const uint4*)(in_c + ((int)(mt_n.z >> 16) << 6));
                    v2 = *(const uint4*)(in_c + ((int)(mt_n.w & 0xFFFFu) << 6));
                    v3 = *(const uint4*)(in_c + ((int)(mt_n.w >> 16) << 6));
                }
                if (i < 6) {   // 2-ahead L1 prefetch (no data registers held)
                    uint4 mt2 = mwarp[i + 2];
                    pf_l1(in_c + ((int)(mt2.z & 0xFFFFu) << 6));
                    pf_l1(in_c + ((int)(mt2.z >> 16) << 6));
                    pf_l1(in_c + ((int)(mt2.w & 0xFFFFu) << 6));
                    pf_l1(in_c + ((int)(mt2.w >> 16) << 6));
                }
                __half2 w0 = __low2half2(u2h2(mt.x));
                __half2 w1 = __high2half2(u2h2(mt.x));
                __half2 w2 = __low2half2(u2h2(mt.y));
                __half2 w3 = __high2half2(u2h2(mt.y));
                __half2 ax = __hmul2(w0, u2h2(u0.x));
                ax = __hfma2(w1, u2h2(u1.x), ax);
                ax = __hfma2(w2, u2h2(u2.x), ax);
                ax = __hfma2(w3, u2h2(u3.x), ax);
                __half2 ay = __hmul2(w0, u2h2(u0.y));
                ay = __hfma2(w1, u2h2(u1.y), ay);
                ay = __hfma2(w2, u2h2(u2.y), ay);
                ay = __hfma2(w3, u2h2(u3.y), ay);
                __half2 az = __hmul2(w0, u2h2(u0.z));
                az = __hfma2(w1, u2h2(u1.z), az);
                az = __hfma2(w2, u2h2(u2.z), az);
                az = __hfma2(w3, u2h2(u3.z), az);
                __half2 aw = __hmul2(w0, u2h2(u0.w));
                aw = __hfma2(w1, u2h2(u1.w), aw);
                aw = __hfma2(w2, u2h2(u2.w), aw);
                aw = __hfma2(w3, u2h2(u3.w), aw);
                int row = wid * 32 + q * 8 + i;
                uint4 st;
                st.x = *reinterpret_cast<uint32_t*>(&ax);
                st.y = *reinterpret_cast<uint32_t*>(&ay);
                st.z = *reinterpret_cast<uint32_t*>(&az);
                st.w = *reinterpret_cast<uint32_t*>(&aw);
                *(uint4*)(A_t + row * A_STRIDE + tx8 * 16) = st;
                mt = mt_n; u0 = v0; u1 = v1; u2 = v2; u3 = v3;
            }
        }
        __syncwarp();   // STS -> LDSM (RAW within warp, cross-lane)

        // ---- GEMM: A frags via ldmatrix, B frags via LDG (L1-resident) ----
        {
            const int mat    = lane >> 3;
            const int row_in = lane & 7;
            const int lrow   = ((mat & 1) << 3) + row_in;
            const int lcolB  = (mat & 2) << 2;
            const uint32_t abase = (uint32_t)(wid * 32 + lrow) * A_STRIDE + (uint32_t)lcolB * 2;
            const uint4* __restrict__ Bg = g_bf + k * 512;

            #pragma unroll
            for (int ks = 0; ks < 4; ks++) {
                uint32_t ah[2][4];
                #pragma unroll
                for (int mi = 0; mi < 2; mi++) {
                    uint32_t addr = abase + (uint32_t)(mi * 16) * A_STRIDE + (uint32_t)(ks * 32);
                    ldsm4(ah[mi], a_u + addr);
                }
                #pragma unroll
                for (int j = 0; j < 4; j++) {
                    uint4 bh = __ldg(Bg + (ks * 4 + j) * 32 + lane);
                    #pragma unroll
                    for (int sub = 0; sub < 2; sub++) {
                        int nt = j * 2 + sub;
                        uint32_t b0 = sub ? bh.z : bh.x;
                        uint32_t b1 = sub ? bh.w : bh.y;
                        mma16816h(acc[0][nt], ah[0], b0, b1);
                        mma16816h(acc[1][nt], ah[1], b0, b1);
                    }
                }
            }
        }
        __syncwarp();   // LDSM (tap k) -> STS (tap k+1): WAR within warp
    }

    // ---- epilogue: stage 32 o-planes at a time in smem, coalesced float4 STG ----
    float* osm = (float*)A_t;                  // 32 x 68 f32 = 8704B <= 9216
    #pragma unroll
    for (int chunk = 0; chunk < 2; chunk++) {
        __syncthreads();   // previous chunk's reads done (and tap-9 A reads done)
        #pragma unroll
        for (int mi = 0; mi < 2; mi++) {
            #pragma unroll
            for (int half = 0; half < 2; half++) {
                int px = wid * 32 + mi * 16 + (lane >> 2) + half * 8;
                #pragma unroll
                for (int jj = 0; jj < 4; jj++) {           // nt within chunk
                    int nt = chunk * 4 + jj;
                    int o  = nt * 8 + (lane & 3) * 2;
                    osm[(o & 31) * 68 + px]       = acc[mi][nt][half * 2 + 0] + __ldg(bias + o);
                    osm[((o + 1) & 31) * 68 + px] = acc[mi][nt][half * 2 + 1] + __ldg(bias + o + 1);
                }
            }
        }
        __syncthreads();
        // store: 32 o-planes x 64 px; out[b][o][p][0..63] contiguous 256B per plane
        float* ob = out + (((size_t)b * 64 + chunk * 32) * 64 + p) * 64;
        #pragma unroll
        for (int r = 0; r < 8; r++) {
            int i  = tid + r * 64;             // [0,512): o32 = i>>4, q4 = (i&15)*4
            int o32 = i >> 4, q4 = (i & 15) * 4;
            float4 v = *(const float4*)(osm + o32 * 68 + q4);
            *(float4*)(ob + (size_t)o32 * 4096 + q4) = v;
        }
    }
}

// ---------------------------------------------------------------------------
// Entry point
// ---------------------------------------------------------------------------
extern "C" void kernel_launch(void* const* d_in, const int* in_sizes, int n_in,
                              void* d_out, int out_size) {
    const float* x      = (const float*)d_in[0];
    const float* offset = (const float*)d_in[1];
    const float* mask   = (const float*)d_in[2];
    const float* weight = (const float*)d_in[3];
    const float* bias   = (const float*)d_in[4];
    float* out = (float*)d_out;

    const int dyn_smem = A_REGION + 1024;      // 10240
    cudaFuncSetAttribute(dcn_main_kernel, cudaFuncAttributeMaxDynamicSharedMemorySize, dyn_smem);

    prep_kernel<<<1024 + 18, 256>>>(x, weight);
    dcn_main_kernel<<<BB * HH * WW / 64, 64, dyn_smem>>>(offset, mask, bias, out);
}

// round 17
// speedup vs baseline: 1.0686x; 1.0686x over previous
#include <cuda_runtime.h>
#include <cuda_fp16.h>
#include <cstdint>

// Shapes fixed by the problem.
#define BB 16
#define CC 64
#define HH 64
#define WW 64
#define CO 64
#define KT 9    // 3x3 taps

// Scratch (__device__ globals: allocation-free rule).
__device__ __half g_nhwc_h[BB * HH * WW * CC];   // [b][y][x][c], fp16
// B fragments (fp16) pre-packed in mma register order:
// idx4 = ((k*4+ks)*4+j)*32 + lane ; uint4 = {nt=2j:(b0,b1), nt=2j+1:(b0,b1)}
__device__ uint4 g_bf[KT * 4 * 4 * 32];          // 4608 uint4 = 72KB

// ---------------------------------------------------------------------------
// helpers
// ---------------------------------------------------------------------------
__device__ __forceinline__ uint32_t smem_u32(const void* p) {
    uint32_t a;
    asm("{ .reg .u64 t; cvta.to.shared.u64 t, %1; cvt.u32.u64 %0, t; }" : "=r"(a) : "l"(p));
    return a;
}
__device__ __forceinline__ void ldsm4(uint32_t* r, uint32_t addr) {
    asm volatile("ldmatrix.sync.aligned.m8n8.x4.shared.b16 {%0,%1,%2,%3}, [%4];"
                 : "=r"(r[0]), "=r"(r[1]), "=r"(r[2]), "=r"(r[3]) : "r"(addr));
}
__device__ __forceinline__ void mma16816h(float* c, const uint32_t* a, uint32_t b0, uint32_t b1) {
    asm volatile("mma.sync.aligned.m16n8k16.row.col.f32.f16.f16.f32 "
                 "{%0,%1,%2,%3}, {%4,%5,%6,%7}, {%8,%9}, {%0,%1,%2,%3};"
                 : "+f"(c[0]), "+f"(c[1]), "+f"(c[2]), "+f"(c[3])
                 : "r"(a[0]), "r"(a[1]), "r"(a[2]), "r"(a[3]), "r"(b0), "r"(b1));
}
__device__ __forceinline__ uint32_t pack_half(float x, float y) {
    __half2 p = __floats2half2_rn(x, y);   // x -> low half
    return *reinterpret_cast<uint32_t*>(&p);
}
__device__ __forceinline__ __half2 u2h2(uint32_t u) {
    return *reinterpret_cast<__half2*>(&u);
}
// B-table load: non-coherent + L1 evict_last (keep the hot shared table pinned
// in L1 while per-CTA gather streams churn the normal ways).
__device__ __forceinline__ uint4 ldg_b_pinned(const uint4* p) {
    uint4 v;
    asm volatile("ld.global.nc.L1::evict_last.v4.u32 {%0,%1,%2,%3}, [%4];"
                 : "=r"(v.x), "=r"(v.y), "=r"(v.z), "=r"(v.w) : "l"(p));
    return v;
}

// ---------------------------------------------------------------------------
// Kernel 1 (merged): blocks [0,1024): NCHW f32 -> NHWC fp16 transpose
//                    blocks [1024,1042): weight -> fp16 B fragments (reg order)
// ---------------------------------------------------------------------------
__global__ void prep_kernel(const float* __restrict__ in, const float* __restrict__ w) {
    if (blockIdx.x < 1024) {
        __shared__ float tile[64][65];
        int by = blockIdx.x;
        int b = by >> 6, y = by & 63;
        #pragma unroll
        for (int i = threadIdx.x; i < 64 * 16; i += 256) {     // float4 loads
            int c = i >> 4, x4 = (i & 15) * 4;
            float4 v = *(const float4*)(in + (((b * 64 + c) * 64 + y) * 64) + x4);
            tile[c][x4 + 0] = v.x; tile[c][x4 + 1] = v.y;
            tile[c][x4 + 2] = v.z; tile[c][x4 + 3] = v.w;
        }
        __syncthreads();
        #pragma unroll
        for (int i = threadIdx.x; i < 64 * 16; i += 256) {     // uint2 stores
            int x = i >> 4, cq = i & 15;
            int c0 = cq * 4;
            uint2 o;
            o.x = pack_half(tile[c0][x],     tile[c0 + 1][x]);
            o.y = pack_half(tile[c0 + 2][x], tile[c0 + 3][x]);
            *reinterpret_cast<uint2*>(g_nhwc_h + (((b * 64 + y) * 64 + x) * 64) + c0) = o;
        }
    } else {
        int idx = (blockIdx.x - 1024) * 256 + threadIdx.x;     // 18 blocks: 4608
        if (idx >= KT * 4 * 4 * 32) return;
        int lane = idx & 31;
        int t = idx >> 5;
        int j  = t & 3;
        int ks = (t >> 2) & 3;
        int k  = t >> 4;
        uint32_t r32[4];
        #pragma unroll
        for (int cmp = 0; cmp < 4; cmp++) {
            int nt = j * 2 + (cmp >> 1);
            int r  = cmp & 1;
            int n  = nt * 8 + (lane >> 2);
            int kk = ks * 16 + r * 8 + (lane & 3) * 2;
            float v0 = w[(n * 64 + kk    ) * 9 + k];
            float v1 = w[(n * 64 + kk + 1) * 9 + k];
            r32[cmp] = pack_half(v0, v1);
        }
        g_bf[idx] = make_uint4(r32[0], r32[1], r32[2], r32[3]);
    }
}

// ---------------------------------------------------------------------------
// Kernel 2: fused deformable sampling (HFMA2) + fp16 HMMA.
// CTA = 64 threads = 2 fully independent warps; tile = 64 px (ONE image row).
// uint4 gather (8 ch/lane, 8 lanes/px), 1-stage data pipeline; B-fragment
// table read with L1 evict_last so it stays resident against gather churn.
// ---------------------------------------------------------------------------
#define A_STRIDE 144   // bytes per A row (72 fp16: pad 64->72, conflict-free ldmatrix)
#define A_REGION 9216  // 64 rows x 144B
#define META_OFF A_REGION

__global__ __launch_bounds__(64, 8)
void dcn_main_kernel(const float* __restrict__ offset,  // (B,18,H,W)
                     const float* __restrict__ mask,    // (B,9,H,W)
                     const float* __restrict__ bias,    // (Cout,)
                     float* __restrict__ out)           // (B,Cout,H,W)
{
    extern __shared__ __align__(16) char smem[];
    char* A_t   = smem;                        // 64 x 144B = 9216
    uint4* Meta = (uint4*)(smem + META_OFF);   // [px] {wAB, wCD, pk01, pk23}

    const int tid  = threadIdx.x;
    const int wid  = tid >> 5;     // 0,1
    const int lane = tid & 31;
    const int tx8  = lane & 7;     // c-chunk (c = tx8*8)
    const int q    = lane >> 3;    // quarter-warp (0..3)

    const int b = blockIdx.x >> 6;
    const int p = blockIdx.x & 63;             // image row

    const uint32_t a_u = smem_u32(A_t);
    const __half* in_b = g_nhwc_h + (size_t)b * 262144;

    // Per-lane pixel and strided offset/mask pointers (k-stride constant).
    const int px_own = wid * 32 + lane;        // 0..63 (column within row p)
    const float* offp = offset + (size_t)b * 18 * 4096 + p * 64 + px_own;
    const float* mskp = mask   + (size_t)b * 9 * 4096  + p * 64 + px_own;

    float acc[2][8][4];
    #pragma unroll
    for (int mi = 0; mi < 2; mi++)
        #pragma unroll
        for (int nt = 0; nt < 8; nt++)
            #pragma unroll
            for (int r = 0; r < 4; r++) acc[mi][nt][r] = 0.f;

    // Pipeline stage: tap-0 offset/mask.
    float nx_oy = offp[0];
    float nx_ox = offp[4096];
    float nx_m  = mskp[0];

    for (int k = 0; k < 9; k++) {
        // ---- consume preloaded offsets; issue tap k+1's loads ----
        float oy = nx_oy, ox = nx_ox, m = nx_m;
        if (k < 8) {
            nx_oy = offp[(k + 1) * 8192];
            nx_ox = offp[(k + 1) * 8192 + 4096];
            nx_m  = mskp[(k + 1) * 4096];
        }

        // ---- per-pixel tap precompute -> meta smem (STS.128, one px per lane) ----
        {
            float py  = oy + (float)(p - 1 + (k / 3));
            float pxx = ox + (float)(px_own - 1 + (k % 3));
            float y0f = floorf(py), x0f = floorf(pxx);
            float wy = py - y0f, wx = pxx - x0f;
            int y0 = (int)y0f, x0 = (int)x0f;
            int y1 = y0 + 1,   x1 = x0 + 1;
            float vy0 = (y0 >= 0 && y0 < 64) ? 1.f : 0.f;
            float vy1 = (y1 >= 0 && y1 < 64) ? 1.f : 0.f;
            float vx0 = (x0 >= 0 && x0 < 64) ? 1.f : 0.f;
            float vx1 = (x1 >= 0 && x1 < 64) ? 1.f : 0.f;
            int y0c = min(max(y0, 0), 63), y1c = min(max(y1, 0), 63);
            int x0c = min(max(x0, 0), 63), x1c = min(max(x1, 0), 63);
            float w0 = m * (1.f - wy) * (1.f - wx) * vy0 * vx0;
            float w1 = m * (1.f - wy) * wx         * vy0 * vx1;
            float w2 = m * wy         * (1.f - wx) * vy1 * vx0;
            float w3 = m * wy         * wx         * vy1 * vx1;
            uint4 mv;
            mv.x = pack_half(w0, w1);
            mv.y = pack_half(w2, w3);
            mv.z = (uint32_t)(y0c * 64 + x0c) | ((uint32_t)(y0c * 64 + x1c) << 16);
            mv.w = (uint32_t)(y1c * 64 + x0c) | ((uint32_t)(y1c * 64 + x1c) << 16);
            Meta[px_own] = mv;
        }
        __syncwarp();   // meta visible to whole warp

        // ---- sampling: 1-stage pipelined uint4 bilinear -> fp16 A tile ----
        {
            const __half* in_c = in_b + tx8 * 8;
            const uint4* mwarp = Meta + wid * 32 + q * 8;    // this quarter's px stream

            uint4 mt = mwarp[0];
            uint4 u0 = *(const uint4*)(in_c + ((int)(mt.z & 0xFFFFu) << 6));
            uint4 u1 = *(const uint4*)(in_c + ((int)(mt.z >> 16) << 6));
            uint4 u2 = *(const uint4*)(in_c + ((int)(mt.w & 0xFFFFu) << 6));
            uint4 u3 = *(const uint4*)(in_c + ((int)(mt.w >> 16) << 6));

            #pragma unroll
            for (int i = 0; i < 8; i++) {
                uint4 mt_n;
                uint4 v0, v1, v2, v3;
                if (i < 7) {   // prefetch next iteration (meta + 4 gathers)
                    mt_n = mwarp[i + 1];
                    v0 = *(const uint4*)(in_c + ((int)(mt_n.z & 0xFFFFu) << 6));
                    v1 = *(const uint4*)(in_c + ((int)(mt_n.z >> 16) << 6));
                    v2 = *(const uint4*)(in_c + ((int)(mt_n.w & 0xFFFFu) << 6));
                    v3 = *(const uint4*)(in_c + ((int)(mt_n.w >> 16) << 6));
                }
                __half2 w0 = __low2half2(u2h2(mt.x));
                __half2 w1 = __high2half2(u2h2(mt.x));
                __half2 w2 = __low2half2(u2h2(mt.y));
                __half2 w3 = __high2half2(u2h2(mt.y));
                __half2 ax = __hmul2(w0, u2h2(u0.x));
                ax = __hfma2(w1, u2h2(u1.x), ax);
                ax = __hfma2(w2, u2h2(u2.x), ax);
                ax = __hfma2(w3, u2h2(u3.x), ax);
                __half2 ay = __hmul2(w0, u2h2(u0.y));
                ay = __hfma2(w1, u2h2(u1.y), ay);
                ay = __hfma2(w2, u2h2(u2.y), ay);
                ay = __hfma2(w3, u2h2(u3.y), ay);
                __half2 az = __hmul2(w0, u2h2(u0.z));
                az = __hfma2(w1, u2h2(u1.z), az);
                az = __hfma2(w2, u2h2(u2.z), az);
                az = __hfma2(w3, u2h2(u3.z), az);
                __half2 aw = __hmul2(w0, u2h2(u0.w));
                aw = __hfma2(w1, u2h2(u1.w), aw);
                aw = __hfma2(w2, u2h2(u2.w), aw);
                aw = __hfma2(w3, u2h2(u3.w), aw);
                int row = wid * 32 + q * 8 + i;
                uint4 st;
                st.x = *reinterpret_cast<uint32_t*>(&ax);
                st.y = *reinterpret_cast<uint32_t*>(&ay);
                st.z = *reinterpret_cast<uint32_t*>(&az);
                st.w = *reinterpret_cast<uint32_t*>(&aw);
                *(uint4*)(A_t + row * A_STRIDE + tx8 * 16) = st;
                mt = mt_n; u0 = v0; u1 = v1; u2 = v2; u3 = v3;
            }
        }
        __syncwarp();   // STS -> LDSM (RAW within warp, cross-lane)

        // ---- GEMM: A frags via ldmatrix, B frags via pinned LDG (L1-resident) ----
        {
            const int mat    = lane >> 3;
            const int row_in = lane & 7;
            const int lrow   = ((mat & 1) << 3) + row_in;
            const int lcolB  = (mat & 2) << 2;
            const uint32_t abase = (uint32_t)(wid * 32 + lrow) * A_STRIDE + (uint32_t)lcolB * 2;
            const uint4* __restrict__ Bg = g_bf + k * 512;

            #pragma unroll
            for (int ks = 0; ks < 4; ks++) {
                uint32_t ah[2][4];
                #pragma unroll
                for (int mi = 0; mi < 2; mi++) {
                    uint32_t addr = abase + (uint32_t)(mi * 16) * A_STRIDE + (uint32_t)(ks * 32);
                    ldsm4(ah[mi], a_u + addr);
                }
                #pragma unroll
                for (int j = 0; j < 4; j++) {
                    uint4 bh = ldg_b_pinned(Bg + (ks * 4 + j) * 32 + lane);
                    #pragma unroll
                    for (int sub = 0; sub < 2; sub++) {
                        int nt = j * 2 + sub;
                        uint32_t b0 = sub ? bh.z : bh.x;
                        uint32_t b1 = sub ? bh.w : bh.y;
                        mma16816h(acc[0][nt], ah[0], b0, b1);
                        mma16816h(acc[1][nt], ah[1], b0, b1);
                    }
                }
            }
        }
        __syncwarp();   // LDSM (tap k) -> STS (tap k+1): WAR within warp
    }

    // ---- epilogue: stage 32 o-planes at a time in smem, coalesced float4 STG ----
    float* osm = (float*)A_t;                  // 32 x 68 f32 = 8704B <= 9216
    #pragma unroll
    for (int chunk = 0; chunk < 2; chunk++) {
        __syncthreads();   // previous chunk's reads done (and tap-9 A reads done)
        #pragma unroll
        for (int mi = 0; mi < 2; mi++) {
            #pragma unroll
            for (int half = 0; half < 2; half++) {
                int px = wid * 32 + mi * 16 + (lane >> 2) + half * 8;
                #pragma unroll
                for (int jj = 0; jj < 4; jj++) {           // nt within chunk
                    int nt = chunk * 4 + jj;
                    int o  = nt * 8 + (lane & 3) * 2;
                    osm[(o & 31) * 68 + px]       = acc[mi][nt][half * 2 + 0] + __ldg(bias + o);
                    osm[((o + 1) & 31) * 68 + px] = acc[mi][nt][half * 2 + 1] + __ldg(bias + o + 1);
                }
            }
        }
        __syncthreads();
        // store: 32 o-planes x 64 px; out[b][o][p][0..63] contiguous 256B per plane
        float* ob = out + (((size_t)b * 64 + chunk * 32) * 64 + p) * 64;
        #pragma unroll
        for (int r = 0; r < 8; r++) {
            int i  = tid + r * 64;             // [0,512): o32 = i>>4, q4 = (i&15)*4
            int o32 = i >> 4, q4 = (i & 15) * 4;
            float4 v = *(const float4*)(osm + o32 * 68 + q4);
            *(float4*)(ob + (size_t)o32 * 4096 + q4) = v;
        }
    }
}

// ---------------------------------------------------------------------------
// Entry point
// ---------------------------------------------------------------------------
extern "C" void kernel_launch(void* const* d_in, const int* in_sizes, int n_in,
                              void* d_out, int out_size) {
    const float* x      = (const float*)d_in[0];
    const float* offset = (const float*)d_in[1];
    const float* mask   = (const float*)d_in[2];
    const float* weight = (const float*)d_in[3];
    const float* bias   = (const float*)d_in[4];
    float* out = (float*)d_out;

    const int dyn_smem = A_REGION + 1024;      // 10240
    cudaFuncSetAttribute(dcn_main_kernel, cudaFuncAttributeMaxDynamicSharedMemorySize, dyn_smem);

    prep_kernel<<<1024 + 18, 256>>>(x, weight);
    dcn_main_kernel<<<BB * HH * WW / 64, 64, dyn_smem>>>(offset, mask, bias, out);
}